// round 15
// baseline (speedup 1.0000x reference)
#include <cuda_runtime.h>

#define N_VOX 1000000
#define KVOL  27
#define C_IN  3
#define C_HID 64
#define C_OUT 3
#define BN_EPS 1e-5f
#define PBLK  64     // points per block: 8 warps x 8 points
#define FULLM 0xffffffffu

// Scratch (device globals: allocation-free per harness rules)
__device__ float g_h[(size_t)N_VOX * C_HID];   // 256 MB: conv1 out (pre-BN)
__device__ float g_stats[4 * C_HID];           // sum, sumsq, scale, shift

typedef unsigned long long u64;

__device__ __forceinline__ u64 pack2(float lo, float hi) {
    u64 r; asm("mov.b64 %0, {%1, %2};" : "=l"(r) : "f"(lo), "f"(hi)); return r;
}
__device__ __forceinline__ void unpack2(u64 v, float& lo, float& hi) {
    asm("mov.b64 {%0, %1}, %2;" : "=f"(lo), "=f"(hi) : "l"(v));
}
#define FMA2(d, a, b, c) asm("fma.rn.f32x2 %0, %1, %2, %3;" : "=l"(d) : "l"(a), "l"(b), "l"(c))

__device__ __forceinline__ u64 relu2(u64 v) {
    float a, b; unpack2(v, a, b);
    return pack2(fmaxf(a, 0.f), fmaxf(b, 0.f));
}

// ---------------------------------------------------------------------------
__global__ void zero_stats_kernel() {
    int i = threadIdx.x;
    if (i < 2 * C_HID) g_stats[i] = 0.f;
}
__global__ void dummy_kernel() {}   // keeps conv1 at ncu capture index 3

// ---------------------------------------------------------------------------
// conv1 (warp = 8 points, uniform union-k loop, zero-fill sparsity):
// h[n,:] = sum_{valid k} feats[nbr[k,n]] @ W1[k]
// Lane owns channel pair `lane`. Staging fills fs4[k][pl] (0 if invalid) and
// per-point masks. Hot loop: warp-uniform ffs over the 8-point union mask;
// per union-k, 3 LDS.64 weight loads serve 8 points; 8 broadcast LDS.128 feats;
// 24 unconditional FMA2 (invalid points contribute 0). Fused BN-stats.
__global__ __launch_bounds__(256, 4) void conv1_kernel(const float* __restrict__ feats,
                                                       const float* __restrict__ W1,
                                                       const int*   __restrict__ nbr) {
    __shared__ u64 w1s[KVOL * 96];          // 20.7 KB straight copy [k*96+c*32+p]
    __shared__ float4 fs4[KVOL * PBLK];     // 27 KB gathered feats (0 if invalid)
    __shared__ unsigned mskP[PBLK];
    __shared__ float st_sm[2 * C_HID];
    const int tid = threadIdx.x;
    {
        const u64* w1g = (const u64*)W1;
        for (int i = tid; i < KVOL * 96; i += 256) w1s[i] = w1g[i];
    }
    if (tid < PBLK) mskP[tid] = 0;
    if (tid < 2 * C_HID) st_sm[tid] = 0.f;
    for (int i = tid; i < KVOL * PBLK; i += 256) fs4[i] = make_float4(0.f, 0.f, 0.f, 0.f);
    __syncthreads();

    const int base = blockIdx.x * PBLK;     // grid divides exactly: no bounds checks
    for (int i = tid; i < KVOL * PBLK; i += 256) {
        int k = i >> 6, pl = i & 63;
        int id = __ldg(&nbr[(size_t)k * N_VOX + base + pl]);
        if (id >= 0) {
            fs4[i] = make_float4(__ldg(&feats[3 * id + 0]),
                                 __ldg(&feats[3 * id + 1]),
                                 __ldg(&feats[3 * id + 2]), 0.f);
            atomicOr(&mskP[pl], 1u << k);
        }
    }
    __syncthreads();

    const int lane = tid & 31;
    const int wrp  = tid >> 5;

    // 8-point union mask (warp-uniform)
    unsigned m = (lane < 8) ? mskP[wrp * 8 + lane] : 0u;
    m |= __shfl_xor_sync(FULLM, m, 4);
    m |= __shfl_xor_sync(FULLM, m, 2);
    m |= __shfl_xor_sync(FULLM, m, 1);
    unsigned mu = __shfl_sync(FULLM, m, 0);

    u64 acc[8];
    #pragma unroll
    for (int g = 0; g < 8; g++) acc[g] = 0ull;

    while (mu) {                            // uniform loop: no divergence
        int k = __ffs(mu) - 1;
        mu &= mu - 1;
        const u64* wk = w1s + k * 96;
        u64 w0 = wk[lane], w1v = wk[32 + lane], w2v = wk[64 + lane];
        const float4* fb = fs4 + k * PBLK + wrp * 8;
        #pragma unroll
        for (int g = 0; g < 8; g++) {
            float4 f = fb[g];               // broadcast LDS.128
            u64 a0 = pack2(f.x, f.x), a1 = pack2(f.y, f.y), a2 = pack2(f.z, f.z);
            FMA2(acc[g], a0, w0,  acc[g]);
            FMA2(acc[g], a1, w1v, acc[g]);
            FMA2(acc[g], a2, w2v, acc[g]);
        }
    }

    // store + fused stats
    u64 ss = 0ull, qq = 0ull;
    const u64 ONE2 = pack2(1.f, 1.f);
    #pragma unroll
    for (int g = 0; g < 8; g++) {
        int n = base + wrp * 8 + g;
        ((u64*)(g_h + (size_t)n * C_HID))[lane] = acc[g];   // 256B coalesced
        FMA2(ss, acc[g], ONE2,   ss);
        FMA2(qq, acc[g], acc[g], qq);
    }
    float a, b, c, d;
    unpack2(ss, a, b);
    unpack2(qq, c, d);
    atomicAdd(&st_sm[2 * lane + 0], a);
    atomicAdd(&st_sm[2 * lane + 1], b);
    atomicAdd(&st_sm[C_HID + 2 * lane + 0], c);
    atomicAdd(&st_sm[C_HID + 2 * lane + 1], d);
    __syncthreads();
    if (tid < 2 * C_HID) atomicAdd(&g_stats[tid], st_sm[tid]);
}

// ---------------------------------------------------------------------------
__global__ void finalize_kernel(const float* __restrict__ gamma,
                                const float* __restrict__ beta) {
    int d = threadIdx.x;
    if (d < C_HID) {
        float mu  = g_stats[d] * (1.f / N_VOX);
        float var = g_stats[C_HID + d] * (1.f / N_VOX) - mu * mu;
        float sc  = gamma[d] * rsqrtf(var + BN_EPS);
        g_stats[2 * C_HID + d] = sc;
        g_stats[3 * C_HID + d] = beta[d] - mu * sc;
    }
}

// ---------------------------------------------------------------------------
// conv2 (warp = 8 points, uniform union-k loop):
// out[n] = sum_k relu(bn(h[nbr[k,n]])) @ W2[26-k]
// Per union-k: 3 LDS.64 weights serve 8 points; per point a broadcast idx,
// predicated h-row LDG (warp-uniform predicate -> no traffic when invalid),
// BN+ReLU then select-zero, 3 FMA2 into acc[8][3].
__global__ __launch_bounds__(256, 3) void conv2_kernel(const float* __restrict__ W2,
                                                       const int*   __restrict__ nbr,
                                                       float* __restrict__ out) {
    __shared__ u64 w2t[KVOL * 96];          // [k*96+c*32+p]: wt[k][c][d]=W2[26-k][d][c]
    __shared__ int idxs[KVOL * PBLK];
    __shared__ unsigned mskP[PBLK];
    const int tid = threadIdx.x;
    {
        float* fp = (float*)w2t;
        for (int i = tid; i < KVOL * C_OUT * C_HID; i += 256) {
            int k   = i / (C_OUT * C_HID);
            int rem = i % (C_OUT * C_HID);
            int c   = rem / C_HID;
            int d   = rem % C_HID;
            fp[(k * 3 + c) * C_HID + d] =
                W2[(size_t)(KVOL - 1 - k) * (C_HID * C_OUT) + d * C_OUT + c];
        }
    }
    if (tid < PBLK) mskP[tid] = 0;
    __syncthreads();

    const int base = blockIdx.x * PBLK;
    for (int i = tid; i < KVOL * PBLK; i += 256) {
        int k = i >> 6, pl = i & 63;
        int id = __ldg(&nbr[(size_t)k * N_VOX + base + pl]);
        idxs[i] = id;
        if (id >= 0) atomicOr(&mskP[pl], 1u << k);
    }
    __syncthreads();

    const int lane = tid & 31;
    const int wrp  = tid >> 5;

    unsigned m = (lane < 8) ? mskP[wrp * 8 + lane] : 0u;
    m |= __shfl_xor_sync(FULLM, m, 4);
    m |= __shfl_xor_sync(FULLM, m, 2);
    m |= __shfl_xor_sync(FULLM, m, 1);
    unsigned mu = __shfl_sync(FULLM, m, 0);

    const u64 scp = pack2(g_stats[2 * C_HID + 2 * lane], g_stats[2 * C_HID + 2 * lane + 1]);
    const u64 shp = pack2(g_stats[3 * C_HID + 2 * lane], g_stats[3 * C_HID + 2 * lane + 1]);

    u64 acc[8][3];
    #pragma unroll
    for (int g = 0; g < 8; g++) { acc[g][0] = 0ull; acc[g][1] = 0ull; acc[g][2] = 0ull; }

    while (mu) {                            // uniform loop
        int k = __ffs(mu) - 1;
        mu &= mu - 1;
        const u64* wk = w2t + k * 96;
        u64 w0 = wk[lane], w1v = wk[32 + lane], w2v = wk[64 + lane];
        const int* ib = idxs + k * PBLK + wrp * 8;
        #pragma unroll
        for (int g = 0; g < 8; g++) {
            int id = ib[g];                 // broadcast LDS.32 (warp-uniform)
            u64 hv = 0ull;
            if (id >= 0)                    // uniform predicate -> @P LDG
                hv = __ldg((const u64*)(g_h + (size_t)id * C_HID) + lane);
            u64 hb = hv;
            FMA2(hb, hb, scp, shp);
            hb = relu2(hb);
            if (id < 0) hb = 0ull;          // relu(shift) must not leak
            FMA2(acc[g][0], hb, w0,  acc[g][0]);
            FMA2(acc[g][1], hb, w1v, acc[g][1]);
            FMA2(acc[g][2], hb, w2v, acc[g][2]);
        }
    }

    #pragma unroll
    for (int g = 0; g < 8; g++) {
        int n = base + wrp * 8 + g;
        float r0, r1, r2;
        { float lo, hi; unpack2(acc[g][0], lo, hi); r0 = lo + hi; }
        { float lo, hi; unpack2(acc[g][1], lo, hi); r1 = lo + hi; }
        { float lo, hi; unpack2(acc[g][2], lo, hi); r2 = lo + hi; }
        #pragma unroll
        for (int o = 16; o >= 1; o >>= 1) {
            r0 += __shfl_xor_sync(FULLM, r0, o);
            r1 += __shfl_xor_sync(FULLM, r1, o);
            r2 += __shfl_xor_sync(FULLM, r2, o);
        }
        if (lane == 0) {
            out[3 * n + 0] = r0;
            out[3 * n + 1] = r1;
            out[3 * n + 2] = r2;
        }
    }
}

// ---------------------------------------------------------------------------
extern "C" void kernel_launch(void* const* d_in, const int* in_sizes, int n_in,
                              void* d_out, int out_size) {
    const float* feats = (const float*)d_in[0];
    const float* W1    = (const float*)d_in[1];
    const float* gamma = (const float*)d_in[2];
    const float* beta  = (const float*)d_in[3];
    const float* W2    = (const float*)d_in[4];
    const int*   nbr   = (const int*)  d_in[5];
    float*       out   = (float*)d_out;

    const int nblk = N_VOX / PBLK;          // 15625 exactly

    zero_stats_kernel<<<1, 128>>>();                    // 0
    dummy_kernel<<<1, 32>>>();                          // 1
    dummy_kernel<<<1, 32>>>();                          // 2
    conv1_kernel<<<nblk, 256>>>(feats, W1, nbr);        // 3 <- ncu
    finalize_kernel<<<1, 64>>>(gamma, beta);            // 4
    conv2_kernel<<<nblk, 256>>>(W2, nbr, out);          // 5
}